// round 9
// baseline (speedup 1.0000x reference)
#include <cuda_runtime.h>
#include <math.h>

// ---------------- problem constants ----------------
#define Pn      50
#define NNODES  3200
#define EPGn    2048
#define En      131072
#define Bn      64
#define NPGn    50
#define D_LIN   1024
#define D_CONV  12544
#define D_REL   256
#define Kk      10
#define Xx      100

// node GEMM split-K: total K = 1024 + 12544 = 13568 = 53 * 256
#define NSEG    53
#define KSEG    256
#define BK      32
#define BM      128

// ---------------- device scratch (static, no allocation) ----------------
__device__ float g_part[(size_t)NSEG * NNODES * Pn];   // 33.9 MB split-K partials
__device__ float g_node[NNODES * Pn];                  // node features [3200,50]
__device__ float g_relT[(size_t)Pn * En];              // rel GEMM output, transposed [50, E]
__device__ float g_logits[Bn * Pn];
__device__ int   g_amax[Bn * Pn];
__device__ unsigned char g_srcl[En];
__device__ unsigned char g_dstl[En];
__device__ int   g_src[En];
__device__ int   g_dst[En];
__device__ float g_L1W[Pn];
__device__ float g_L1R[Pn];
__device__ int   g_is64;

// ---------------- dtype detection for relation_indexes ----------------
// If int64: words are [lo,hi,lo,hi,...] with hi always 0 (values < 3200).
// If int32: odd words are src[1],src[3],... uniform in [0,50) -> all-zero prob ~0.
__global__ void detect_k(const int* __restrict__ ri) {
    int nz = 0;
    for (int i = 0; i < 64; i++) nz |= ri[2 * i + 1];
    g_is64 = (nz == 0) ? 1 : 0;
}

__global__ void prep_k(const int* __restrict__ ri) {
    int e = blockIdx.x * blockDim.x + threadIdx.x;
    if (e >= En) return;
    int s, d;
    if (g_is64) {
        s = (int)((const long long*)ri)[e];
        d = (int)((const long long*)ri)[En + e];
    } else {
        s = ri[e];
        d = ri[En + e];
    }
    g_src[e] = s;
    g_dst[e] = d;
    int b = e >> 11;  // e / EPGn
    g_srcl[e] = (unsigned char)(s - b * NPGn);
    g_dstl[e] = (unsigned char)(d - b * NPGn);
}

// ---------------- column L1 norms of the weight matrices ----------------
__global__ void l1_k(const float* __restrict__ Wo, const float* __restrict__ Wc,
                     const float* __restrict__ Wr) {
    int c = blockIdx.x;
    int t = threadIdx.x;  // 256 threads
    float sw = 0.f, sr = 0.f;
    for (int dd = t; dd < D_LIN; dd += 256)  sw += fabsf(Wo[dd * Pn + c]);
    for (int dd = t; dd < D_CONV; dd += 256) sw += fabsf(Wc[dd * Pn + c]);
    if (t < D_REL) sr = fabsf(Wr[t * Pn + c]);
    __shared__ float shw[256];
    __shared__ float shr[256];
    shw[t] = sw; shr[t] = sr;
    __syncthreads();
    for (int o = 128; o > 0; o >>= 1) {
        if (t < o) { shw[t] += shw[t + o]; shr[t] += shr[t + o]; }
        __syncthreads();
    }
    if (t == 0) { g_L1W[c] = shw[0]; g_L1R[c] = shr[0]; }
}

// ---------------- node GEMM: node = obj_lin @ W_obj + obj_conv @ W_conv ----------------
// grid (25, 53), block 64. Each thread computes 2 rows x 50 cols in registers.
// Seg s covers K range [s*256, s*256+256): segs 0..3 -> obj_lin, 4..52 -> obj_conv
// (boundary at 1024 = 4*256 falls exactly on a segment boundary).
__global__ void __launch_bounds__(64) node_gemm_k(
    const float* __restrict__ obj_lin, const float* __restrict__ obj_conv,
    const float* __restrict__ Wo, const float* __restrict__ Wc) {
    __shared__ float Asm[BM][BK + 1];
    __shared__ float Wsm[BK][Pn + 2];
    int t = threadIdx.x;
    int row0 = blockIdx.x * BM;
    int s = blockIdx.y;
    const float* A;
    const float* W;
    int lda;
    if (s < 4) { A = obj_lin + (size_t)s * KSEG; lda = D_LIN; W = Wo + (size_t)s * KSEG * Pn; }
    else       { A = obj_conv + (size_t)(s * KSEG - D_LIN); lda = D_CONV; W = Wc + (size_t)(s * KSEG - D_LIN) * Pn; }

    float acc0[Pn], acc1[Pn];
#pragma unroll
    for (int c = 0; c < Pn; c++) { acc0[c] = 0.f; acc1[c] = 0.f; }

    for (int tile = 0; tile < KSEG / BK; tile++) {
        int kb = tile * BK;
        // A tile 128x32 via float4, coalesced
#pragma unroll
        for (int j = 0; j < 16; j++) {
            int i4 = t + 64 * j;
            int r = i4 >> 3, c4 = i4 & 7;
            float4 v = *reinterpret_cast<const float4*>(&A[(size_t)(row0 + r) * lda + kb + c4 * 4]);
            Asm[r][c4 * 4 + 0] = v.x;
            Asm[r][c4 * 4 + 1] = v.y;
            Asm[r][c4 * 4 + 2] = v.z;
            Asm[r][c4 * 4 + 3] = v.w;
        }
        // W tile 32x50
        for (int j = t; j < BK * Pn; j += 64) {
            int kk = j / Pn, c = j % Pn;
            Wsm[kk][c] = W[(size_t)(kb + kk) * Pn + c];
        }
        __syncthreads();
#pragma unroll 2
        for (int kk = 0; kk < BK; kk++) {
            float a0 = Asm[t][kk];
            float a1 = Asm[t + 64][kk];
#pragma unroll
            for (int c = 0; c < Pn; c++) {
                float w = Wsm[kk][c];
                acc0[c] = fmaf(a0, w, acc0[c]);
                acc1[c] = fmaf(a1, w, acc1[c]);
            }
        }
        __syncthreads();
    }
    float* o0 = g_part + ((size_t)s * NNODES + row0 + t) * Pn;
    float* o1 = o0 + (size_t)64 * Pn;
#pragma unroll
    for (int c = 0; c < Pn; c++) { o0[c] = acc0[c]; o1[c] = acc1[c]; }
}

__global__ void node_reduce_k() {
    int i = blockIdx.x * 256 + threadIdx.x;
    if (i >= NNODES * Pn) return;
    float s = 0.f;
    for (int seg = 0; seg < NSEG; seg++) s += g_part[(size_t)seg * NNODES * Pn + i];
    g_node[i] = s;
}

// ---------------- rel GEMM: relT[c][e] = (rel_lin @ W_rel)[e][c] ----------------
// grid 1024, block 64. K=256 = 8 tiles of 32. Output stored transposed for
// coalesced reads in the edge-max kernel.
__global__ void __launch_bounds__(64) rel_gemm_k(
    const float* __restrict__ rel_lin, const float* __restrict__ Wr) {
    __shared__ float Asm[BM][BK + 1];
    __shared__ float Wsm[BK][Pn + 2];
    int t = threadIdx.x;
    int row0 = blockIdx.x * BM;

    float acc0[Pn], acc1[Pn];
#pragma unroll
    for (int c = 0; c < Pn; c++) { acc0[c] = 0.f; acc1[c] = 0.f; }

    for (int tile = 0; tile < D_REL / BK; tile++) {
        int kb = tile * BK;
#pragma unroll
        for (int j = 0; j < 16; j++) {
            int i4 = t + 64 * j;
            int r = i4 >> 3, c4 = i4 & 7;
            float4 v = *reinterpret_cast<const float4*>(&rel_lin[(size_t)(row0 + r) * D_REL + kb + c4 * 4]);
            Asm[r][c4 * 4 + 0] = v.x;
            Asm[r][c4 * 4 + 1] = v.y;
            Asm[r][c4 * 4 + 2] = v.z;
            Asm[r][c4 * 4 + 3] = v.w;
        }
        for (int j = t; j < BK * Pn; j += 64) {
            int kk = j / Pn, c = j % Pn;
            Wsm[kk][c] = Wr[(size_t)(kb + kk) * Pn + c];
        }
        __syncthreads();
#pragma unroll 2
        for (int kk = 0; kk < BK; kk++) {
            float a0 = Asm[t][kk];
            float a1 = Asm[t + 64][kk];
#pragma unroll
            for (int c = 0; c < Pn; c++) {
                float w = Wsm[kk][c];
                acc0[c] = fmaf(a0, w, acc0[c]);
                acc1[c] = fmaf(a1, w, acc1[c]);
            }
        }
        __syncthreads();
    }
    int e0 = row0 + t;
#pragma unroll
    for (int c = 0; c < Pn; c++) {
        g_relT[(size_t)c * En + e0] = acc0[c];
        g_relT[(size_t)c * En + e0 + 64] = acc1[c];
    }
}

// ---------------- per (graph, class) max over 2048 edges, with argmax ----------------
__global__ void edge_max_k() {
    int bc = blockIdx.x;
    int b = bc / Pn, c = bc % Pn;
    __shared__ float nodesm[NPGn];
    int t = threadIdx.x;  // 256
    if (t < NPGn) nodesm[t] = g_node[(b * NPGn + t) * Pn + c];
    __syncthreads();
    const float* rptr = g_relT + (size_t)c * En + (size_t)b * EPGn;
    const unsigned char* sp = g_srcl + (size_t)b * EPGn;
    const unsigned char* dp = g_dstl + (size_t)b * EPGn;
    float best = -3.402823466e38f;
    int bi = 0;
    for (int e = t; e < EPGn; e += 256) {
        float v = rptr[e] + nodesm[sp[e]] + nodesm[dp[e]];
        if (v > best) { best = v; bi = e; }  // strict > keeps lowest index on ties
    }
    __shared__ float sv[256];
    __shared__ int si[256];
    sv[t] = best; si[t] = bi;
    __syncthreads();
    for (int o = 128; o > 0; o >>= 1) {
        if (t < o) {
            float v2 = sv[t + o];
            int i2 = si[t + o];
            if (v2 > sv[t] || (v2 == sv[t] && i2 < si[t])) { sv[t] = v2; si[t] = i2; }
        }
        __syncthreads();
    }
    if (t == 0) { g_logits[bc] = sv[0]; g_amax[bc] = si[0]; }
}

// ---------------- final: top-K classes, analytic relevances, top-X, outputs ----------------
// One block (1 warp) per graph. Only ~10 nonzero relation scores exist per graph:
// rank them descending; remaining ranks are zeros in ascending flat-index order
// (jax.lax.top_k tie-break).
__global__ void final_k(float* __restrict__ out) {
    int b = blockIdx.x;
    __shared__ float s_p[Kk];
    __shared__ int s_cls[Kk];
    __shared__ float s_val[Kk];
    __shared__ int s_fi[Kk];
    __shared__ int s_m;

    if (threadIdx.x == 0) {
        float pr[Pn];
        bool used[Pn];
        for (int c = 0; c < Pn; c++) {
            float x = g_logits[b * Pn + c];
            pr[c] = 1.f / (1.f + expf(-x));
            used[c] = false;
        }
        // top-10 classes by prob (strict > keeps lowest index on ties)
        for (int k = 0; k < Kk; k++) {
            int bcx = 0;
            float bv = -1.f;
            for (int c = 0; c < Pn; c++)
                if (!used[c] && pr[c] > bv) { bv = pr[c]; bcx = c; }
            used[bcx] = true;
            s_cls[k] = bcx;
            s_p[k] = bv;
        }
        // analytic relation scores at the argmax edge of each top class
        float tv[Kk];
        int tf[Kk];
        for (int k = 0; k < Kk; k++) {
            int c = s_cls[k];
            float x = g_logits[b * Pn + c];
            float p = s_p[k];
            float q = 1.f / (1.f + expf(x));   // 1 - p, computed stably
            float sg = p * q;                   // sigmoid'
            int eloc = g_amax[b * Pn + c];
            int eg = b * EPGn + eloc;
            float mult = (g_srcl[eg] == g_dstl[eg]) ? 2.f : 1.f;
            float rn = mult * sg * g_L1W[c];
            float re = sg * g_L1R[c];
            tv[k] = rn * re * rn * p;
            tf[k] = eloc * Kk + k;
        }
        // insertion sort: value desc, flat-index asc on ties
        for (int i = 1; i < Kk; i++) {
            float v = tv[i];
            int f = tf[i];
            int j = i - 1;
            while (j >= 0 && (tv[j] < v || (tv[j] == v && tf[j] > f))) {
                tv[j + 1] = tv[j]; tf[j + 1] = tf[j]; j--;
            }
            tv[j + 1] = v; tf[j + 1] = f;
        }
        int m = 0;
        while (m < Kk && tv[m] > 0.f) m++;
        for (int k = 0; k < Kk; k++) { s_val[k] = tv[k]; s_fi[k] = tf[k]; }
        s_m = m;
    }
    __syncthreads();

    int m = s_m;
    for (int r = threadIdx.x; r < Xx; r += blockDim.x) {
        float val;
        int fi;
        if (r < m) {
            val = s_val[r];
            fi = s_fi[r];
        } else {
            // z-th smallest flat index not occupied by a positive special:
            // fixed point of x = z + |{f in posset : f <= x}|
            int z = r - m;
            int x = z;
            for (int it = 0; it < Kk + 2; it++) {
                int cnt = 0;
                for (int i = 0; i < m; i++) cnt += (s_fi[i] <= x) ? 1 : 0;
                int nx = z + cnt;
                if (nx == x) break;
                x = nx;
            }
            val = 0.f;
            fi = x;
        }
        int k = fi % Kk;
        int eloc = fi / Kk;
        int eg = b * EPGn + eloc;
        int o = b * Xx + r;
        out[o]          = val;                      // relation_scores_sorted
        out[6400 + o]   = (float)g_src[eg];         // relation_indexes_sorted[0]
        out[12800 + o]  = (float)g_dst[eg];         // relation_indexes_sorted[1]
        out[19200 + o]  = s_p[k];                   // predicate_scores_sorted
        out[25600 + o]  = (float)s_cls[k];          // predicate_classes_sorted
    }
    if (threadIdx.x == 0) out[32000 + b] = 100.f;   // n_relations
}

// ---------------- launcher ----------------
extern "C" void kernel_launch(void* const* d_in, const int* in_sizes, int n_in,
                              void* d_out, int out_size) {
    const float* obj_lin  = (const float*)d_in[0];
    const float* obj_conv = (const float*)d_in[1];
    const float* rel_lin  = (const float*)d_in[2];
    const int*   ri       = (const int*)d_in[3];
    const float* W_obj    = (const float*)d_in[4];
    const float* W_conv   = (const float*)d_in[5];
    const float* W_rel    = (const float*)d_in[6];
    float* out = (float*)d_out;

    detect_k<<<1, 1>>>(ri);
    prep_k<<<(En + 255) / 256, 256>>>(ri);
    l1_k<<<Pn, 256>>>(W_obj, W_conv, W_rel);
    node_gemm_k<<<dim3(NNODES / BM, NSEG), 64>>>(obj_lin, obj_conv, W_obj, W_conv);
    node_reduce_k<<<(NNODES * Pn + 255) / 256, 256>>>();
    rel_gemm_k<<<En / BM, 64>>>(rel_lin, W_rel);
    edge_max_k<<<Bn * Pn, 256>>>();
    final_k<<<Bn, 32>>>(out);
}

// round 10
// speedup vs baseline: 1.3159x; 1.3159x over previous
#include <cuda_runtime.h>
#include <math.h>

// ---------------- problem constants ----------------
#define Pn      50
#define NNODES  3200
#define EPGn    2048
#define En      131072
#define Bn      64
#define NPGn    50
#define D_LIN   1024
#define D_CONV  12544
#define D_REL   256
#define Kk      10
#define Xx      100

// node GEMM split-K: total K = 1024 + 12544 = 13568 = 53 * 256
#define NSEG    53
#define KSEG    256
#define BK      32
#define BM      128
#define PW      56      // padded P (50 -> 56) so both 28-col halves are 16B aligned
#define APITCH  33      // A smem pitch in float2 (duplicated pairs), conflict-free

// ---------------- device scratch (static, no allocation) ----------------
__device__ float g_part[(size_t)NSEG * NNODES * Pn];   // split-K partials
__device__ float g_node[NNODES * Pn];                  // node features [3200,50]
__device__ float g_relT[(size_t)Pn * En];              // rel GEMM output, transposed [50, E]
__device__ float g_logits[Bn * Pn];
__device__ int   g_amax[Bn * Pn];
__device__ unsigned char g_srcl[En];
__device__ unsigned char g_dstl[En];
__device__ int   g_src[En];
__device__ int   g_dst[En];
__device__ float g_L1W[Pn];
__device__ float g_L1R[Pn];
__device__ int   g_is64;

// packed f32x2 FMA (SASS FFMA2): d.lo += a.lo*b.lo; d.hi += a.hi*b.hi
#define FMA2(d, a, b) \
    asm("fma.rn.f32x2 %0, %1, %2, %0;" : "+l"(d) : "l"(a), "l"(b))

// ---------------- dtype detection for relation_indexes ----------------
__global__ void detect_k(const int* __restrict__ ri) {
    int nz = 0;
    for (int i = 0; i < 64; i++) nz |= ri[2 * i + 1];
    g_is64 = (nz == 0) ? 1 : 0;
}

__global__ void prep_k(const int* __restrict__ ri) {
    int e = blockIdx.x * blockDim.x + threadIdx.x;
    if (e >= En) return;
    int s, d;
    if (g_is64) {
        s = (int)((const long long*)ri)[e];
        d = (int)((const long long*)ri)[En + e];
    } else {
        s = ri[e];
        d = ri[En + e];
    }
    g_src[e] = s;
    g_dst[e] = d;
    int b = e >> 11;
    g_srcl[e] = (unsigned char)(s - b * NPGn);
    g_dstl[e] = (unsigned char)(d - b * NPGn);
}

// ---------------- column L1 norms of the weight matrices ----------------
__global__ void l1_k(const float* __restrict__ Wo, const float* __restrict__ Wc,
                     const float* __restrict__ Wr) {
    int c = blockIdx.x;
    int t = threadIdx.x;  // 256 threads
    float sw = 0.f, sr = 0.f;
    for (int dd = t; dd < D_LIN; dd += 256)  sw += fabsf(Wo[dd * Pn + c]);
    for (int dd = t; dd < D_CONV; dd += 256) sw += fabsf(Wc[dd * Pn + c]);
    if (t < D_REL) sr = fabsf(Wr[t * Pn + c]);
    __shared__ float shw[256];
    __shared__ float shr[256];
    shw[t] = sw; shr[t] = sr;
    __syncthreads();
    for (int o = 128; o > 0; o >>= 1) {
        if (t < o) { shw[t] += shw[t + o]; shr[t] += shr[t + o]; }
        __syncthreads();
    }
    if (t == 0) { g_L1W[c] = shw[0]; g_L1R[c] = shr[0]; }
}

// ================= shared GEMM tile body =================
// Block: 128 threads = 64 row-threads x 2 col-halves (28 cols each, P padded to 56).
// Each thread: rows (row0+r, row0+r+64), 28 cols -> 14 f32x2 accumulators per row.
// A tile stored duplicated in smem as (a,a) float2 so the FFMA2 broadcast operand
// needs no packing. Per kk: 2 LDS.64 (a) + 7 LDS.128 (w, warp-broadcast) + 28 FFMA2.
struct GemmAcc {
    unsigned long long acc0[14];
    unsigned long long acc1[14];
};

__device__ __forceinline__ void gemm_tiles(
    const float* __restrict__ A, int lda,
    const float* __restrict__ W,   // [K, 50] row-major, tile rows contiguous
    int ntiles, int row0, int t,
    float2* Ad, float* Wsm, GemmAcc& g) {

    int r  = t & 63;
    int c0 = (t >> 6) * 28;

    unsigned adbase = (unsigned)__cvta_generic_to_shared(Ad);
    unsigned a0base = adbase + (unsigned)(r * (APITCH * 8));
    unsigned a1base = adbase + (unsigned)((r + 64) * (APITCH * 8));
    unsigned wbase  = (unsigned)__cvta_generic_to_shared(Wsm) + (unsigned)(c0 * 4);

#pragma unroll
    for (int i = 0; i < 14; i++) { g.acc0[i] = 0ULL; g.acc1[i] = 0ULL; }

    // zero the pad columns (50..55) once
    for (int j = t; j < BK * 6; j += 128) Wsm[(j / 6) * PW + 50 + (j % 6)] = 0.f;

    for (int tile = 0; tile < ntiles; tile++) {
        int kb = tile * BK;
        // ---- A tile: 128 rows x 32 k, float4 global loads, duplicated smem store
#pragma unroll
        for (int j = 0; j < 8; j++) {
            int idx = t + 128 * j;
            int rr = idx >> 3, q = idx & 7;
            float4 v = *reinterpret_cast<const float4*>(&A[(size_t)(row0 + rr) * lda + kb + q * 4]);
            float2* dst = &Ad[rr * APITCH + q * 4];
            dst[0] = make_float2(v.x, v.x);
            dst[1] = make_float2(v.y, v.y);
            dst[2] = make_float2(v.z, v.z);
            dst[3] = make_float2(v.w, v.w);
        }
        // ---- W tile: 32x50 contiguous span in global -> padded [32][56]
        {
            const float* Wt = W + (size_t)kb * Pn;
#pragma unroll
            for (int j2 = t; j2 < (BK * Pn) / 2; j2 += 128) {
                int j = j2 * 2;
                int kk = j / Pn;
                int c = j - kk * Pn;
                *reinterpret_cast<float2*>(&Wsm[kk * PW + c]) =
                    *reinterpret_cast<const float2*>(&Wt[j]);
            }
        }
        __syncthreads();

#pragma unroll 8
        for (int kk = 0; kk < BK; kk++) {
            unsigned long long a0, a1;
            asm("ld.shared.b64 %0, [%1];" : "=l"(a0) : "r"(a0base + kk * 8));
            asm("ld.shared.b64 %0, [%1];" : "=l"(a1) : "r"(a1base + kk * 8));
#pragma unroll
            for (int cq = 0; cq < 7; cq++) {
                unsigned long long w0, w1;
                asm("ld.shared.v2.u64 {%0, %1}, [%2];"
                    : "=l"(w0), "=l"(w1)
                    : "r"(wbase + kk * (PW * 4) + cq * 16));
                FMA2(g.acc0[2 * cq],     a0, w0);
                FMA2(g.acc0[2 * cq + 1], a0, w1);
                FMA2(g.acc1[2 * cq],     a1, w0);
                FMA2(g.acc1[2 * cq + 1], a1, w1);
            }
        }
        __syncthreads();
    }
}

__device__ __forceinline__ void unpack2(unsigned long long v, float& lo, float& hi) {
    asm("mov.b64 {%0, %1}, %2;" : "=f"(lo), "=f"(hi) : "l"(v));
}

// ---------------- node GEMM: node = obj_lin @ W_obj + obj_conv @ W_conv ----------------
// grid (25, 53), block 128. Seg s covers K range [s*256, (s+1)*256):
// segs 0..3 -> obj_lin, 4..52 -> obj_conv (boundary at 1024 = 4*256).
__global__ void __launch_bounds__(128) node_gemm_k(
    const float* __restrict__ obj_lin, const float* __restrict__ obj_conv,
    const float* __restrict__ Wo, const float* __restrict__ Wc) {
    __shared__ float2 Ad[BM * APITCH];
    __shared__ float  Wsm[BK * PW];
    int t = threadIdx.x;
    int row0 = blockIdx.x * BM;
    int s = blockIdx.y;
    const float* A;
    const float* W;
    int lda;
    if (s < 4) { A = obj_lin + (size_t)s * KSEG; lda = D_LIN; W = Wo + (size_t)s * KSEG * Pn; }
    else       { A = obj_conv + (size_t)(s * KSEG - D_LIN); lda = D_CONV; W = Wc + (size_t)(s * KSEG - D_LIN) * Pn; }

    GemmAcc g;
    gemm_tiles(A, lda, W, KSEG / BK, row0, t, Ad, Wsm, g);

    int r = t & 63;
    int c0 = (t >> 6) * 28;
    float* o0 = g_part + ((size_t)s * NNODES + row0 + r) * Pn;
    float* o1 = o0 + (size_t)64 * Pn;
#pragma unroll
    for (int cq = 0; cq < 14; cq++) {
        int c = c0 + 2 * cq;
        float lo, hi;
        unpack2(g.acc0[cq], lo, hi);
        if (c < Pn)     o0[c] = lo;
        if (c + 1 < Pn) o0[c + 1] = hi;
        unpack2(g.acc1[cq], lo, hi);
        if (c < Pn)     o1[c] = lo;
        if (c + 1 < Pn) o1[c + 1] = hi;
    }
}

__global__ void node_reduce_k() {
    int i = blockIdx.x * 256 + threadIdx.x;
    if (i >= NNODES * Pn) return;
    float s = 0.f;
    for (int seg = 0; seg < NSEG; seg++) s += g_part[(size_t)seg * NNODES * Pn + i];
    g_node[i] = s;
}

// ---------------- rel GEMM: relT[c][e] = (rel_lin @ W_rel)[e][c] ----------------
// grid 1024, block 128. K=256 = 8 tiles. Output transposed for coalesced edge-max reads.
__global__ void __launch_bounds__(128) rel_gemm_k(
    const float* __restrict__ rel_lin, const float* __restrict__ Wr) {
    __shared__ float2 Ad[BM * APITCH];
    __shared__ float  Wsm[BK * PW];
    int t = threadIdx.x;
    int row0 = blockIdx.x * BM;

    GemmAcc g;
    gemm_tiles(rel_lin, D_REL, Wr, D_REL / BK, row0, t, Ad, Wsm, g);

    int r = t & 63;
    int c0 = (t >> 6) * 28;
    int e0 = row0 + r;
#pragma unroll
    for (int cq = 0; cq < 14; cq++) {
        int c = c0 + 2 * cq;
        float lo, hi;
        unpack2(g.acc0[cq], lo, hi);
        if (c < Pn)     g_relT[(size_t)c * En + e0] = lo;
        if (c + 1 < Pn) g_relT[(size_t)(c + 1) * En + e0] = hi;
        unpack2(g.acc1[cq], lo, hi);
        if (c < Pn)     g_relT[(size_t)c * En + e0 + 64] = lo;
        if (c + 1 < Pn) g_relT[(size_t)(c + 1) * En + e0 + 64] = hi;
    }
}

// ---------------- per (graph, class) max over 2048 edges, with argmax ----------------
__global__ void edge_max_k() {
    int bc = blockIdx.x;
    int b = bc / Pn, c = bc % Pn;
    __shared__ float nodesm[NPGn];
    int t = threadIdx.x;  // 256
    if (t < NPGn) nodesm[t] = g_node[(b * NPGn + t) * Pn + c];
    __syncthreads();
    const float* rptr = g_relT + (size_t)c * En + (size_t)b * EPGn;
    const unsigned char* sp = g_srcl + (size_t)b * EPGn;
    const unsigned char* dp = g_dstl + (size_t)b * EPGn;
    float best = -3.402823466e38f;
    int bi = 0;
    for (int e = t; e < EPGn; e += 256) {
        float v = rptr[e] + nodesm[sp[e]] + nodesm[dp[e]];
        if (v > best) { best = v; bi = e; }  // strict > keeps lowest index on ties
    }
    __shared__ float sv[256];
    __shared__ int si[256];
    sv[t] = best; si[t] = bi;
    __syncthreads();
    for (int o = 128; o > 0; o >>= 1) {
        if (t < o) {
            float v2 = sv[t + o];
            int i2 = si[t + o];
            if (v2 > sv[t] || (v2 == sv[t] && i2 < si[t])) { sv[t] = v2; si[t] = i2; }
        }
        __syncthreads();
    }
    if (t == 0) { g_logits[bc] = sv[0]; g_amax[bc] = si[0]; }
}

// ---------------- final: top-K classes, analytic relevances, top-X, outputs ----------------
__global__ void final_k(float* __restrict__ out) {
    int b = blockIdx.x;
    __shared__ float s_p[Kk];
    __shared__ int s_cls[Kk];
    __shared__ float s_val[Kk];
    __shared__ int s_fi[Kk];
    __shared__ int s_m;

    if (threadIdx.x == 0) {
        float pr[Pn];
        bool used[Pn];
        for (int c = 0; c < Pn; c++) {
            float x = g_logits[b * Pn + c];
            pr[c] = 1.f / (1.f + expf(-x));
            used[c] = false;
        }
        for (int k = 0; k < Kk; k++) {
            int bcx = 0;
            float bv = -1.f;
            for (int c = 0; c < Pn; c++)
                if (!used[c] && pr[c] > bv) { bv = pr[c]; bcx = c; }
            used[bcx] = true;
            s_cls[k] = bcx;
            s_p[k] = bv;
        }
        float tv[Kk];
        int tf[Kk];
        for (int k = 0; k < Kk; k++) {
            int c = s_cls[k];
            float x = g_logits[b * Pn + c];
            float p = s_p[k];
            float q = 1.f / (1.f + expf(x));
            float sg = p * q;
            int eloc = g_amax[b * Pn + c];
            int eg = b * EPGn + eloc;
            float mult = (g_srcl[eg] == g_dstl[eg]) ? 2.f : 1.f;
            float rn = mult * sg * g_L1W[c];
            float re = sg * g_L1R[c];
            tv[k] = rn * re * rn * p;
            tf[k] = eloc * Kk + k;
        }
        for (int i = 1; i < Kk; i++) {
            float v = tv[i];
            int f = tf[i];
            int j = i - 1;
            while (j >= 0 && (tv[j] < v || (tv[j] == v && tf[j] > f))) {
                tv[j + 1] = tv[j]; tf[j + 1] = tf[j]; j--;
            }
            tv[j + 1] = v; tf[j + 1] = f;
        }
        int m = 0;
        while (m < Kk && tv[m] > 0.f) m++;
        for (int k = 0; k < Kk; k++) { s_val[k] = tv[k]; s_fi[k] = tf[k]; }
        s_m = m;
    }
    __syncthreads();

    int m = s_m;
    for (int r = threadIdx.x; r < Xx; r += blockDim.x) {
        float val;
        int fi;
        if (r < m) {
            val = s_val[r];
            fi = s_fi[r];
        } else {
            int z = r - m;
            int x = z;
            for (int it = 0; it < Kk + 2; it++) {
                int cnt = 0;
                for (int i = 0; i < m; i++) cnt += (s_fi[i] <= x) ? 1 : 0;
                int nx = z + cnt;
                if (nx == x) break;
                x = nx;
            }
            val = 0.f;
            fi = x;
        }
        int k = fi % Kk;
        int eloc = fi / Kk;
        int eg = b * EPGn + eloc;
        int o = b * Xx + r;
        out[o]          = val;
        out[6400 + o]   = (float)g_src[eg];
        out[12800 + o]  = (float)g_dst[eg];
        out[19200 + o]  = s_p[k];
        out[25600 + o]  = (float)s_cls[k];
    }
    if (threadIdx.x == 0) out[32000 + b] = 100.f;
}

// ---------------- launcher ----------------
extern "C" void kernel_launch(void* const* d_in, const int* in_sizes, int n_in,
                              void* d_out, int out_size) {
    const float* obj_lin  = (const float*)d_in[0];
    const float* obj_conv = (const float*)d_in[1];
    const float* rel_lin  = (const float*)d_in[2];
    const int*   ri       = (const int*)d_in[3];
    const float* W_obj    = (const float*)d_in[4];
    const float* W_conv   = (const float*)d_in[5];
    const float* W_rel    = (const float*)d_in[6];
    float* out = (float*)d_out;

    detect_k<<<1, 1>>>(ri);
    prep_k<<<(En + 255) / 256, 256>>>(ri);
    l1_k<<<Pn, 256>>>(W_obj, W_conv, W_rel);
    node_gemm_k<<<dim3(NNODES / BM, NSEG), 128>>>(obj_lin, obj_conv, W_obj, W_conv);
    node_reduce_k<<<(NNODES * Pn + 255) / 256, 256>>>();
    rel_gemm_k<<<En / BM, 128>>>(rel_lin, W_rel);
    edge_max_k<<<Bn * Pn, 256>>>();
    final_k<<<Bn, 32>>>(out);
}